// round 16
// baseline (speedup 1.0000x reference)
#include <cuda_runtime.h>
#include <cuda_fp16.h>
#include <cstdint>

// ---------------- problem constants ----------------
#define E_   16
#define B_   4096
#define DX_  128
#define DC_  64
#define DIN_ 192
#define DH_  1024
#define DO_  128

#define BM   128            // batch rows per CTA
#define CHN  32             // DH chunk
#define NCH  (DH_/CHN)      // 32 chunks
#define THREADS 128         // 4 warps x 32 rows; 2 CTAs/SM

// ---------------- smem layout (bytes) ----------------
// xc: 4 row-blocks of 32 rows; per block 12288 B:
//   addr = blk*12288 + kt*1024 + mpair*512 + ((gr^(kt&7))*64) + ct*16 + mhalf*8
// W1 chunk (12288 B): kt*1024 + tnpair*512 + gr*64 + ct*16 + tnhalf*8
// W2 chunk (8192 B):  ks*4096 + tnpair*512 + gr*64 + ct*16 + tnhalf*8
#define XC_BLK   12288
#define W1_BYTES 12288
#define W2_BYTES 8192

#define OFF_XC 0
#define XC_BYTES (4*XC_BLK)            // 49152
#define OFF_W1 (OFF_XC + XC_BYTES)     // 49152
#define OFF_W2 (OFF_W1 + 2*W1_BYTES)   // 73728
#define OFF_B1 (OFF_W2 + 2*W2_BYTES)   // 90112 (fp32 b1, 1024 floats)
#define OFF_B2 (OFF_B1 + DH_*4)        // 94208 (fp32 b2, 128 floats)
#define SMEM_BYTES (OFF_B2 + DO_*4)    // 94720 -> 2 CTAs/SM (189 KB < 227)

// ---------------- prepacked fp16 weights (device globals: allowed) ----------------
__device__ __half g_w1h[(size_t)E_ * DH_ * DIN_];  // 6.3 MB, [e][ch][6144 halves]
__device__ __half g_w2h[(size_t)E_ * DO_ * DH_];   // 4.2 MB, [e][ch][4096 halves]

#define NB1 (E_*DH_*(DIN_/16))     // 196608
#define NB2 (E_*DO_*(DH_/16))      // 131072
#define NBW (NB1+NB2)              // 327680 = 1280*256

// ---------------- helpers ----------------
__device__ __forceinline__ uint32_t s2u(const void* p){
    uint32_t a;
    asm("{ .reg .u64 t; cvta.to.shared.u64 t, %1; cvt.u32.u64 %0, t; }" : "=r"(a) : "l"(p));
    return a;
}
__device__ __forceinline__ uint32_t pkh2(float lo, float hi){
    __half2 h = __floats2half2_rn(lo, hi);       // lo -> lower 16 bits
    return *reinterpret_cast<uint32_t*>(&h);
}
__device__ __forceinline__ void cp16(uint32_t dst, const void* src){
    asm volatile("cp.async.cg.shared.global [%0], [%1], 16;" :: "r"(dst), "l"(src) : "memory");
}
#define CP_COMMIT() asm volatile("cp.async.commit_group;" ::: "memory")
#define CP_WAIT0()  asm volatile("cp.async.wait_group 0;" ::: "memory")

__device__ __forceinline__ void mma_fp16(float c[4],
                                         uint32_t a0, uint32_t a1, uint32_t a2, uint32_t a3,
                                         uint32_t b0, uint32_t b1){
    asm volatile(
        "mma.sync.aligned.m16n8k16.row.col.f32.f16.f16.f32 "
        "{%0,%1,%2,%3}, {%4,%5,%6,%7}, {%8,%9}, {%0,%1,%2,%3};"
        : "+f"(c[0]), "+f"(c[1]), "+f"(c[2]), "+f"(c[3])
        : "r"(a0), "r"(a1), "r"(a2), "r"(a3), "r"(b0), "r"(b1));
}

// frag uint2s for one 16-k block: ct_c = (halves 2c,2c+1 ; halves 2c+8,2c+9)
__device__ __forceinline__ void frag4(const float4 f0, const float4 f1,
                                      const float4 f2, const float4 f3,
                                      uint2& c0, uint2& c1, uint2& c2, uint2& c3){
    c0.x = pkh2(f0.x, f0.y);  c0.y = pkh2(f2.x, f2.y);   // k0,1 | k8,9
    c1.x = pkh2(f0.z, f0.w);  c1.y = pkh2(f2.z, f2.w);   // k2,3 | k10,11
    c2.x = pkh2(f1.x, f1.y);  c2.y = pkh2(f3.x, f3.y);   // k4,5 | k12,13
    c3.x = pkh2(f1.z, f1.w);  c3.y = pkh2(f3.z, f3.w);   // k6,7 | k14,15
}

// ---------------- prepack: fp32 -> fp16, frag-paired chunk layout ----------------
__global__ __launch_bounds__(256)
void prepack_kernel(const float* __restrict__ W1, const float* __restrict__ W2)
{
    const int i = blockIdx.x * 256 + threadIdx.x;
    if (i >= NBW) return;

    if (i < NB1) {
        const int kt = i % 12;
        const int n  = (i / 12) % DH_;
        const int e  = i / (12 * DH_);
        const float* s = W1 + ((size_t)e * DH_ + n) * DIN_ + kt * 16;
        uint2 c0, c1, c2, c3;
        frag4(*(const float4*)(s), *(const float4*)(s + 4),
              *(const float4*)(s + 8), *(const float4*)(s + 12), c0, c1, c2, c3);
        const int ch = n >> 5, nl = n & 31, tn = nl >> 3, g = nl & 7;
        __half* d = g_w1h + (size_t)e * DH_ * DIN_ + ch * 6144
                    + kt * 512 + (tn >> 1) * 256 + g * 32 + (tn & 1) * 4;
        *(uint2*)(d)      = c0;
        *(uint2*)(d + 8)  = c1;
        *(uint2*)(d + 16) = c2;
        *(uint2*)(d + 24) = c3;
    } else {
        const int j = i - NB1;
        const int p = j % 64;              // 16-k block within DH
        const int n = (j / 64) % DO_;
        const int e = j / (64 * DO_);
        const float* s = W2 + ((size_t)e * DO_ + n) * DH_ + p * 16;
        uint2 c0, c1, c2, c3;
        frag4(*(const float4*)(s), *(const float4*)(s + 4),
              *(const float4*)(s + 8), *(const float4*)(s + 12), c0, c1, c2, c3);
        const int ch = p >> 1, ks = p & 1, tn = n >> 3, g = n & 7;
        __half* d = g_w2h + (size_t)e * DO_ * DH_ + ch * 4096
                    + ks * 2048 + (tn >> 1) * 256 + g * 32 + (tn & 1) * 4;
        *(uint2*)(d)      = c0;
        *(uint2*)(d + 8)  = c1;
        *(uint2*)(d + 16) = c2;
        *(uint2*)(d + 24) = c3;
    }
}

// stage one DH chunk of prepacked W1 + W2 (pure linear copy)
__device__ __forceinline__ void stage_w(uint32_t sb, const __half* __restrict__ w1h,
                                        const __half* __restrict__ w2h, int ch, int buf, int tid)
{
    const __half* src1 = w1h + (size_t)ch * 6144;
    const uint32_t d1 = sb + OFF_W1 + buf * W1_BYTES;
    #pragma unroll
    for (int i = 0; i < 6; ++i) {                 // 768 cp16
        const int idx = tid + i * THREADS;
        cp16(d1 + idx * 16, src1 + idx * 8);
    }
    const __half* src2 = w2h + (size_t)ch * 4096;
    const uint32_t d2 = sb + OFF_W2 + buf * W2_BYTES;
    #pragma unroll
    for (int i = 0; i < 4; ++i) {                 // 512 cp16
        const int idx = tid + i * THREADS;
        cp16(d2 + idx * 16, src2 + idx * 8);
    }
}

// ---------------- main kernel ----------------
__global__ __launch_bounds__(THREADS)
void expert_mlp_m32b_kernel(const float* __restrict__ x, const float* __restrict__ cond,
                            const float* __restrict__ b1, const float* __restrict__ b2,
                            float* __restrict__ out)
{
    extern __shared__ char smem[];
    float* s_b1 = (float*)(smem + OFF_B1);
    float* s_b2 = (float*)(smem + OFF_B2);
    const uint32_t sb = s2u(smem);

    const int tid  = threadIdx.x;
    const int lane = tid & 31;
    const int wid  = tid >> 5;           // 0..3, 32 rows each
    const int gr   = lane >> 2;
    const int ct   = lane & 3;

    const int e  = blockIdx.x >> 5;      // 32 CTAs per expert
    const int m0 = (blockIdx.x & 31) * BM;

    const float* xp  = x    + (size_t)e * B_ * DX_ + (size_t)m0 * DX_;
    const float* cp_ = cond + (size_t)e * B_ * DC_ + (size_t)m0 * DC_;
    const __half* w1h = g_w1h + (size_t)e * DH_ * DIN_;
    const __half* w2h = g_w2h + (size_t)e * DO_ * DH_;
    float*        op  = out  + (size_t)e * B_ * DO_ + (size_t)m0 * DO_;

    // stage chunk-0 weights (overlaps with xc conversion below)
    stage_w(sb, w1h, w2h, 0, 0, tid);
    CP_COMMIT();

    // biases (fp32): b1 = 1024 floats = 128 threads x float4 x 2 passes
    #pragma unroll
    for (int i = 0; i < 2; ++i) {
        const int t = tid + i * THREADS;
        const float4 v = *(const float4*)(b1 + (size_t)e * DH_ + t * 4);
        *(float4*)(s_b1 + t * 4) = v;
    }
    if (tid < 32) {
        const float4 w = *(const float4*)(b2 + (size_t)e * DO_ + tid * 4);
        *(float4*)(s_b2 + tid * 4) = w;
    }

    // convert xc: fp32 gmem -> fp16 frag-paired smem. 128 rows x 12 blocks of 16 k
    #pragma unroll
    for (int i = 0; i < 12; ++i) {
        const int gi = tid + i * THREADS;          // 1536 blocks
        const int r  = gi / 12, p = gi % 12;
        const float* s = (p < 8) ? (xp + (size_t)r * DX_ + p * 16)
                                 : (cp_ + (size_t)r * DC_ + (p - 8) * 16);
        uint2 c0, c1, c2, c3;
        frag4(*(const float4*)(s), *(const float4*)(s + 4),
              *(const float4*)(s + 8), *(const float4*)(s + 12), c0, c1, c2, c3);
        const int w = r >> 5, r32 = r & 31, m = r32 >> 3, g = r32 & 7;
        char* d = smem + OFF_XC + w * XC_BLK + p * 1024 + (m >> 1) * 512
                  + ((g ^ (p & 7)) * 64) + (m & 1) * 8;
        *(uint2*)(d)      = c0;
        *(uint2*)(d + 16) = c1;
        *(uint2*)(d + 32) = c2;
        *(uint2*)(d + 48) = c3;
    }
    // correct cp.async handshake: drain ALL own copies, THEN publish
    CP_WAIT0();
    __syncthreads();

    // ---- hybrid A placement: kt 0..5 fragments in regs (48 regs), kt 6..11 from smem ----
    // warp w owns rows 32w..32w+31 = xc block w; m-frag f at mpair offset f*512
    const char* xb = smem + OFF_XC + wid * XC_BLK + ct * 16;
    uint4 xa[12];                       // [kt][mfrag]: index 2*kt+f, kt<6
    #pragma unroll
    for (int kt = 0; kt < 6; ++kt) {
        const int gx = ((gr ^ (kt & 7)) << 6);
        xa[2*kt]   = *(const uint4*)(xb + kt * 1024 + gx);
        xa[2*kt+1] = *(const uint4*)(xb + kt * 1024 + 512 + gx);
    }

    // y accumulators: warp owns 32 rows x 128 cols -> 2 m-frags x 16 n-tiles x 4 regs
    float yacc[2][16][4];
    #pragma unroll
    for (int m = 0; m < 2; ++m)
        #pragma unroll
        for (int t = 0; t < 16; ++t)
            #pragma unroll
            for (int c = 0; c < 4; ++c) yacc[m][t][c] = 0.0f;

    const int arow = wid * 32 + gr;      // lower A row of m-frag 0 (m-frag 1: +16)
    const int bfo = gr * 64 + ct * 16;   // B-frag lane offset

    for (int ch = 0; ch < NCH; ++ch) {
        const int buf = ch & 1;

        // stage next chunk into buf^1 (readers finished last iteration)
        if (ch + 1 < NCH) {
            stage_w(sb, w1h, w2h, ch + 1, buf ^ 1, tid);
            CP_COMMIT();
        }

        const char* w1s = smem + OFF_W1 + buf * W1_BYTES;
        const char* w2s = smem + OFF_W2 + buf * W2_BYTES;

        // ---- MMA1: h[32x32] = xc @ W1chunk^T  (12 k16-steps) ----
        float hacc[2][4][4];
        #pragma unroll
        for (int m = 0; m < 2; ++m)
            #pragma unroll
            for (int t = 0; t < 4; ++t)
                #pragma unroll
                for (int c = 0; c < 4; ++c) hacc[m][t][c] = 0.0f;

        #pragma unroll
        for (int kt = 0; kt < 12; ++kt) {
            uint4 a0, a1;
            if (kt < 6) {
                a0 = xa[2*kt];
                a1 = xa[2*kt+1];
            } else {
                const int gx = ((gr ^ (kt & 7)) << 6);
                a0 = *(const uint4*)(xb + kt * 1024 + gx);
                a1 = *(const uint4*)(xb + kt * 1024 + 512 + gx);
            }
            const uint4 b01 = *(const uint4*)(w1s + kt * 1024 + bfo);        // tn0, tn1
            const uint4 b23 = *(const uint4*)(w1s + kt * 1024 + 512 + bfo);  // tn2, tn3
            mma_fp16(hacc[0][0], a0.x, a0.z, a0.y, a0.w, b01.x, b01.y);
            mma_fp16(hacc[0][1], a0.x, a0.z, a0.y, a0.w, b01.z, b01.w);
            mma_fp16(hacc[0][2], a0.x, a0.z, a0.y, a0.w, b23.x, b23.y);
            mma_fp16(hacc[0][3], a0.x, a0.z, a0.y, a0.w, b23.z, b23.w);
            mma_fp16(hacc[1][0], a1.x, a1.z, a1.y, a1.w, b01.x, b01.y);
            mma_fp16(hacc[1][1], a1.x, a1.z, a1.y, a1.w, b01.z, b01.w);
            mma_fp16(hacc[1][2], a1.x, a1.z, a1.y, a1.w, b23.x, b23.y);
            mma_fp16(hacc[1][3], a1.x, a1.z, a1.y, a1.w, b23.z, b23.w);
        }

        // ---- register epilogue: relu(h + b1) -> fp16 pairs (frag-ready) ----
        uint32_t pk[2][4][2];
        const float* b1s = s_b1 + ch * CHN;
        #pragma unroll
        for (int t = 0; t < 4; ++t) {
            const float2 bb = *(const float2*)(b1s + t * 8 + 2 * ct);
            #pragma unroll
            for (int m = 0; m < 2; ++m) {
                pk[m][t][0] = pkh2(fmaxf(hacc[m][t][0] + bb.x, 0.0f),
                                   fmaxf(hacc[m][t][1] + bb.y, 0.0f));   // row gr(+16m)
                pk[m][t][1] = pkh2(fmaxf(hacc[m][t][2] + bb.x, 0.0f),
                                   fmaxf(hacc[m][t][3] + bb.y, 0.0f));   // row gr+8(+16m)
            }
        }

        // ---- MMA2: y[32x128] += h(frags in regs) @ W2chunk^T (2 k16-steps) ----
        #pragma unroll
        for (int ks = 0; ks < 2; ++ks) {
            const char* base = w2s + ks * 4096 + bfo;
            const uint32_t a00 = pk[0][2*ks][0],   a01v = pk[0][2*ks][1];
            const uint32_t a02 = pk[0][2*ks+1][0], a03  = pk[0][2*ks+1][1];
            const uint32_t a10 = pk[1][2*ks][0],   a11  = pk[1][2*ks][1];
            const uint32_t a12 = pk[1][2*ks+1][0], a13  = pk[1][2*ks+1][1];
            #pragma unroll
            for (int tp = 0; tp < 8; ++tp) {
                const uint4 bw = *(const uint4*)(base + tp * 512);    // tn=2tp, 2tp+1
                mma_fp16(yacc[0][2*tp],   a00, a01v, a02, a03, bw.x, bw.y);
                mma_fp16(yacc[0][2*tp+1], a00, a01v, a02, a03, bw.z, bw.w);
                mma_fp16(yacc[1][2*tp],   a10, a11, a12, a13, bw.x, bw.y);
                mma_fp16(yacc[1][2*tp+1], a10, a11, a12, a13, bw.z, bw.w);
            }
        }

        // drain my copies of chunk ch+1, then publish to all threads.
        CP_WAIT0();
        __syncthreads();
    }

    // ---- final epilogue: y + b2 -> gmem ----
    #pragma unroll
    for (int tn = 0; tn < 16; ++tn) {
        const int col = tn * 8 + 2 * ct;
        const float2 bb = *(const float2*)(s_b2 + col);
        #pragma unroll
        for (int m = 0; m < 2; ++m) {
            const int row = arow + m * 16;
            float2 lo, hi;
            lo.x = yacc[m][tn][0] + bb.x;
            lo.y = yacc[m][tn][1] + bb.y;
            hi.x = yacc[m][tn][2] + bb.x;
            hi.y = yacc[m][tn][3] + bb.y;
            *(float2*)(op + (size_t)row * DO_ + col)       = lo;
            *(float2*)(op + (size_t)(row + 8) * DO_ + col) = hi;
        }
    }
}

extern "C" void kernel_launch(void* const* d_in, const int* in_sizes, int n_in,
                              void* d_out, int out_size)
{
    const float* x    = (const float*)d_in[0];
    const float* cond = (const float*)d_in[1];
    const float* W1   = (const float*)d_in[2];
    const float* b1   = (const float*)d_in[3];
    const float* W2   = (const float*)d_in[4];
    const float* b2   = (const float*)d_in[5];
    float* out = (float*)d_out;

    prepack_kernel<<<NBW / 256, 256>>>(W1, W2);

    cudaFuncSetAttribute(expert_mlp_m32b_kernel,
                         cudaFuncAttributeMaxDynamicSharedMemorySize, SMEM_BYTES);
    const int grid = E_ * (B_ / BM);   // 512 CTAs -> 2 per SM
    expert_mlp_m32b_kernel<<<grid, THREADS, SMEM_BYTES>>>(x, cond, b1, b2, out);
}

// round 17
// speedup vs baseline: 1.1395x; 1.1395x over previous
#include <cuda_runtime.h>
#include <cuda_fp16.h>
#include <cstdint>

// ---------------- problem constants ----------------
#define E_   16
#define B_   4096
#define DX_  128
#define DC_  64
#define DIN_ 192
#define DH_  1024
#define DO_  128

#define BM   64             // batch rows per CTA
#define CHN  64             // DH chunk (doubled: half the barriers)
#define NCH  (DH_/CHN)      // 16 chunks
#define THREADS 128         // 4 warps x 16 rows; 2 CTAs/SM

// ---------------- smem layout (bytes) ----------------
// xc: 2 row-blocks of 32 rows; per block 12288 B:
//   addr = blk*12288 + kt*1024 + mpair*512 + ((gr^(kt&7))*64) + ct*16 + mhalf*8
// W1 chunk (24576 B): kt*2048 + tnpair*512 + gr*64 + ct*16 + tnhalf*8   (tn 0..7)
// W2 chunk (16384 B): ks*4096  + tnpair*512 + gr*64 + ct*16 + tnhalf*8   (ks 0..3)
#define XC_BLK   12288
#define W1_BYTES 24576
#define W2_BYTES 16384

#define OFF_XC 0
#define XC_BYTES (2*XC_BLK)            // 24576
#define OFF_W1 (OFF_XC + XC_BYTES)     // 24576
#define OFF_W2 (OFF_W1 + 2*W1_BYTES)   // 73728
#define OFF_B1 (OFF_W2 + 2*W2_BYTES)   // 106496 (fp32 b1, 1024 floats)
#define OFF_B2 (OFF_B1 + DH_*4)        // 110592 (fp32 b2, 128 floats)
#define SMEM_BYTES (OFF_B2 + DO_*4)    // 111104 -> 2 CTAs/SM (222KB <= 228KB)

// ---------------- prepacked fp16 weights (device globals: allowed) ----------------
__device__ __half g_w1h[(size_t)E_ * DH_ * DIN_];  // 6.3 MB, [e][ch][12288 halves]
__device__ __half g_w2h[(size_t)E_ * DO_ * DH_];   // 4.2 MB, [e][ch][8192 halves]

#define NB1 (E_*DH_*(DIN_/16))     // 196608
#define NB2 (E_*DO_*(DH_/16))      // 131072
#define NBW (NB1+NB2)              // 327680 = 1280*256

// ---------------- helpers ----------------
__device__ __forceinline__ uint32_t s2u(const void* p){
    uint32_t a;
    asm("{ .reg .u64 t; cvta.to.shared.u64 t, %1; cvt.u32.u64 %0, t; }" : "=r"(a) : "l"(p));
    return a;
}
__device__ __forceinline__ uint32_t pkh2(float lo, float hi){
    __half2 h = __floats2half2_rn(lo, hi);       // lo -> lower 16 bits
    return *reinterpret_cast<uint32_t*>(&h);
}
__device__ __forceinline__ void cp16(uint32_t dst, const void* src){
    asm volatile("cp.async.cg.shared.global [%0], [%1], 16;" :: "r"(dst), "l"(src) : "memory");
}
#define CP_COMMIT() asm volatile("cp.async.commit_group;" ::: "memory")
#define CP_WAIT0()  asm volatile("cp.async.wait_group 0;" ::: "memory")

__device__ __forceinline__ void mma_fp16(float c[4],
                                         uint32_t a0, uint32_t a1, uint32_t a2, uint32_t a3,
                                         uint32_t b0, uint32_t b1){
    asm volatile(
        "mma.sync.aligned.m16n8k16.row.col.f32.f16.f16.f32 "
        "{%0,%1,%2,%3}, {%4,%5,%6,%7}, {%8,%9}, {%0,%1,%2,%3};"
        : "+f"(c[0]), "+f"(c[1]), "+f"(c[2]), "+f"(c[3])
        : "r"(a0), "r"(a1), "r"(a2), "r"(a3), "r"(b0), "r"(b1));
}

// frag uint2s for one 16-k block: ct_c = (halves 2c,2c+1 ; halves 2c+8,2c+9)
__device__ __forceinline__ void frag4(const float4 f0, const float4 f1,
                                      const float4 f2, const float4 f3,
                                      uint2& c0, uint2& c1, uint2& c2, uint2& c3){
    c0.x = pkh2(f0.x, f0.y);  c0.y = pkh2(f2.x, f2.y);   // k0,1 | k8,9
    c1.x = pkh2(f0.z, f0.w);  c1.y = pkh2(f2.z, f2.w);   // k2,3 | k10,11
    c2.x = pkh2(f1.x, f1.y);  c2.y = pkh2(f3.x, f3.y);   // k4,5 | k12,13
    c3.x = pkh2(f1.z, f1.w);  c3.y = pkh2(f3.z, f3.w);   // k6,7 | k14,15
}

// ---------------- prepack: fp32 -> fp16, frag-paired chunk layout (CHN=64) ----------------
__global__ __launch_bounds__(256)
void prepack_kernel(const float* __restrict__ W1, const float* __restrict__ W2)
{
    const int i = blockIdx.x * 256 + threadIdx.x;
    if (i >= NBW) return;

    if (i < NB1) {
        const int kt = i % 12;
        const int n  = (i / 12) % DH_;
        const int e  = i / (12 * DH_);
        const float* s = W1 + ((size_t)e * DH_ + n) * DIN_ + kt * 16;
        uint2 c0, c1, c2, c3;
        frag4(*(const float4*)(s), *(const float4*)(s + 4),
              *(const float4*)(s + 8), *(const float4*)(s + 12), c0, c1, c2, c3);
        const int ch = n >> 6, nl = n & 63, tn = nl >> 3, g = nl & 7;
        __half* d = g_w1h + (size_t)e * DH_ * DIN_ + ch * 12288
                    + kt * 1024 + (tn >> 1) * 256 + g * 32 + (tn & 1) * 4;
        *(uint2*)(d)      = c0;
        *(uint2*)(d + 8)  = c1;
        *(uint2*)(d + 16) = c2;
        *(uint2*)(d + 24) = c3;
    } else {
        const int j = i - NB1;
        const int p = j % 64;              // 16-k block within DH
        const int n = (j / 64) % DO_;
        const int e = j / (64 * DO_);
        const float* s = W2 + ((size_t)e * DO_ + n) * DH_ + p * 16;
        uint2 c0, c1, c2, c3;
        frag4(*(const float4*)(s), *(const float4*)(s + 4),
              *(const float4*)(s + 8), *(const float4*)(s + 12), c0, c1, c2, c3);
        const int ch = p >> 2, ks = p & 3, tn = n >> 3, g = n & 7;
        __half* d = g_w2h + (size_t)e * DO_ * DH_ + ch * 8192
                    + ks * 2048 + (tn >> 1) * 256 + g * 32 + (tn & 1) * 4;
        *(uint2*)(d)      = c0;
        *(uint2*)(d + 8)  = c1;
        *(uint2*)(d + 16) = c2;
        *(uint2*)(d + 24) = c3;
    }
}

// stage one DH chunk of prepacked W1 + W2 (pure linear copy)
__device__ __forceinline__ void stage_w(uint32_t sb, const __half* __restrict__ w1h,
                                        const __half* __restrict__ w2h, int ch, int buf, int tid)
{
    const __half* src1 = w1h + (size_t)ch * 12288;
    const uint32_t d1 = sb + OFF_W1 + buf * W1_BYTES;
    #pragma unroll
    for (int i = 0; i < 12; ++i) {                // 1536 cp16
        const int idx = tid + i * THREADS;
        cp16(d1 + idx * 16, src1 + idx * 8);
    }
    const __half* src2 = w2h + (size_t)ch * 8192;
    const uint32_t d2 = sb + OFF_W2 + buf * W2_BYTES;
    #pragma unroll
    for (int i = 0; i < 8; ++i) {                 // 1024 cp16
        const int idx = tid + i * THREADS;
        cp16(d2 + idx * 16, src2 + idx * 8);
    }
}

// ---------------- main kernel ----------------
__global__ __launch_bounds__(THREADS)
void expert_mlp_c64_kernel(const float* __restrict__ x, const float* __restrict__ cond,
                           const float* __restrict__ b1, const float* __restrict__ b2,
                           float* __restrict__ out)
{
    extern __shared__ char smem[];
    float* s_b1 = (float*)(smem + OFF_B1);
    float* s_b2 = (float*)(smem + OFF_B2);
    const uint32_t sb = s2u(smem);

    const int tid  = threadIdx.x;
    const int lane = tid & 31;
    const int wid  = tid >> 5;           // 0..3, 16 rows each
    const int gr   = lane >> 2;
    const int ct   = lane & 3;

    const int e  = blockIdx.x >> 6;      // 64 CTAs per expert
    const int m0 = (blockIdx.x & 63) * BM;

    const float* xp  = x    + (size_t)e * B_ * DX_ + (size_t)m0 * DX_;
    const float* cp_ = cond + (size_t)e * B_ * DC_ + (size_t)m0 * DC_;
    const __half* w1h = g_w1h + (size_t)e * DH_ * DIN_;
    const __half* w2h = g_w2h + (size_t)e * DO_ * DH_;
    float*        op  = out  + (size_t)e * B_ * DO_ + (size_t)m0 * DO_;

    // stage chunk-0 weights (overlaps with xc conversion below)
    stage_w(sb, w1h, w2h, 0, 0, tid);
    CP_COMMIT();

    // biases (fp32): b1 = 1024 floats = 128 threads x float4 x 2 passes
    #pragma unroll
    for (int i = 0; i < 2; ++i) {
        const int t = tid + i * THREADS;
        const float4 v = *(const float4*)(b1 + (size_t)e * DH_ + t * 4);
        *(float4*)(s_b1 + t * 4) = v;
    }
    if (tid < 32) {
        const float4 w = *(const float4*)(b2 + (size_t)e * DO_ + tid * 4);
        *(float4*)(s_b2 + tid * 4) = w;
    }

    // convert xc: fp32 gmem -> fp16 frag-paired smem. 64 rows x 12 blocks of 16 k
    #pragma unroll
    for (int i = 0; i < 6; ++i) {
        const int gi = tid + i * THREADS;          // 768 blocks
        const int r  = gi / 12, p = gi % 12;
        const float* s = (p < 8) ? (xp + (size_t)r * DX_ + p * 16)
                                 : (cp_ + (size_t)r * DC_ + (p - 8) * 16);
        uint2 c0, c1, c2, c3;
        frag4(*(const float4*)(s), *(const float4*)(s + 4),
              *(const float4*)(s + 8), *(const float4*)(s + 12), c0, c1, c2, c3);
        const int w = r >> 5, r32 = r & 31, m = r32 >> 3, g = r32 & 7;
        char* d = smem + OFF_XC + w * XC_BLK + p * 1024 + (m >> 1) * 512
                  + ((g ^ (p & 7)) * 64) + (m & 1) * 8;
        *(uint2*)(d)      = c0;
        *(uint2*)(d + 16) = c1;
        *(uint2*)(d + 32) = c2;
        *(uint2*)(d + 48) = c3;
    }
    // correct cp.async handshake: drain ALL own copies, THEN publish
    CP_WAIT0();
    __syncthreads();

    // ---- load this warp's A fragments ONCE into registers (48 regs) ----
    uint4 xa[12];
    {
        const char* xb = smem + OFF_XC + (wid >> 1) * XC_BLK + (wid & 1) * 512 + ct * 16;
        #pragma unroll
        for (int kt = 0; kt < 12; ++kt)
            xa[kt] = *(const uint4*)(xb + kt * 1024 + ((gr ^ (kt & 7)) << 6));
    }

    // y accumulators: warp owns 16 rows x 128 cols -> 16 n-tiles x 4 regs
    float yacc[16][4];
    #pragma unroll
    for (int t = 0; t < 16; ++t)
        #pragma unroll
        for (int c = 0; c < 4; ++c) yacc[t][c] = 0.0f;

    const int arow = wid * 16 + gr;      // this thread's lower A row
    const int bfo = gr * 64 + ct * 16;   // B-frag lane offset

    for (int ch = 0; ch < NCH; ++ch) {
        const int buf = ch & 1;

        // stage next chunk into buf^1 (readers finished last iteration)
        if (ch + 1 < NCH) {
            stage_w(sb, w1h, w2h, ch + 1, buf ^ 1, tid);
            CP_COMMIT();
        }

        const char* w1s = smem + OFF_W1 + buf * W1_BYTES;
        const char* w2s = smem + OFF_W2 + buf * W2_BYTES;

        // ---- MMA1: h[16x64] = xc(regs) @ W1chunk^T  (12 k16-steps x 8 tn) ----
        float hacc[8][4];
        #pragma unroll
        for (int t = 0; t < 8; ++t)
            #pragma unroll
            for (int c = 0; c < 4; ++c) hacc[t][c] = 0.0f;

        #pragma unroll
        for (int kt = 0; kt < 12; ++kt) {
            const char* wb = w1s + kt * 2048 + bfo;
            const uint4 a = xa[kt];
            const uint4 b01 = *(const uint4*)(wb);          // tn0, tn1
            const uint4 b23 = *(const uint4*)(wb + 512);    // tn2, tn3
            const uint4 b45 = *(const uint4*)(wb + 1024);   // tn4, tn5
            const uint4 b67 = *(const uint4*)(wb + 1536);   // tn6, tn7
            mma_fp16(hacc[0], a.x, a.z, a.y, a.w, b01.x, b01.y);
            mma_fp16(hacc[1], a.x, a.z, a.y, a.w, b01.z, b01.w);
            mma_fp16(hacc[2], a.x, a.z, a.y, a.w, b23.x, b23.y);
            mma_fp16(hacc[3], a.x, a.z, a.y, a.w, b23.z, b23.w);
            mma_fp16(hacc[4], a.x, a.z, a.y, a.w, b45.x, b45.y);
            mma_fp16(hacc[5], a.x, a.z, a.y, a.w, b45.z, b45.w);
            mma_fp16(hacc[6], a.x, a.z, a.y, a.w, b67.x, b67.y);
            mma_fp16(hacc[7], a.x, a.z, a.y, a.w, b67.z, b67.w);
        }

        // ---- register epilogue: relu(h + b1) -> fp16 pairs (frag-ready) ----
        uint32_t pk[8][2];
        const float* b1s = s_b1 + ch * CHN;
        #pragma unroll
        for (int t = 0; t < 8; ++t) {
            const float2 bb = *(const float2*)(b1s + t * 8 + 2 * ct);
            pk[t][0] = pkh2(fmaxf(hacc[t][0] + bb.x, 0.0f),
                            fmaxf(hacc[t][1] + bb.y, 0.0f));   // row gr
            pk[t][1] = pkh2(fmaxf(hacc[t][2] + bb.x, 0.0f),
                            fmaxf(hacc[t][3] + bb.y, 0.0f));   // row gr+8
        }

        // ---- MMA2: y[16x128] += h(frags in regs) @ W2chunk^T (4 k16-steps) ----
        #pragma unroll
        for (int ks = 0; ks < 4; ++ks) {
            const char* base = w2s + ks * 4096 + bfo;
            const uint32_t a0 = pk[2*ks][0],   a1 = pk[2*ks][1];
            const uint32_t a2 = pk[2*ks+1][0], a3 = pk[2*ks+1][1];
            #pragma unroll
            for (int tp = 0; tp < 8; ++tp) {
                const uint4 bw = *(const uint4*)(base + tp * 512);    // tn=2tp, 2tp+1
                mma_fp16(yacc[2*tp],   a0, a1, a2, a3, bw.x, bw.y);
                mma_fp16(yacc[2*tp+1], a0, a1, a2, a3, bw.z, bw.w);
            }
        }

        // drain my copies of chunk ch+1, then publish to all threads.
        CP_WAIT0();
        __syncthreads();
    }

    // ---- final epilogue: y + b2 -> gmem ----
    #pragma unroll
    for (int tn = 0; tn < 16; ++tn) {
        const int col = tn * 8 + 2 * ct;
        const float2 bb = *(const float2*)(s_b2 + col);
        float2 lo, hi;
        lo.x = yacc[tn][0] + bb.x;
        lo.y = yacc[tn][1] + bb.y;
        hi.x = yacc[tn][2] + bb.x;
        hi.y = yacc[tn][3] + bb.y;
        *(float2*)(op + (size_t)arow * DO_ + col)       = lo;
        *(float2*)(op + (size_t)(arow + 8) * DO_ + col) = hi;
    }
}

extern "C" void kernel_launch(void* const* d_in, const int* in_sizes, int n_in,
                              void* d_out, int out_size)
{
    const float* x    = (const float*)d_in[0];
    const float* cond = (const float*)d_in[1];
    const float* W1   = (const float*)d_in[2];
    const float* b1   = (const float*)d_in[3];
    const float* W2   = (const float*)d_in[4];
    const float* b2   = (const float*)d_in[5];
    float* out = (float*)d_out;

    prepack_kernel<<<NBW / 256, 256>>>(W1, W2);

    cudaFuncSetAttribute(expert_mlp_c64_kernel,
                         cudaFuncAttributeMaxDynamicSharedMemorySize, SMEM_BYTES);
    const int grid = E_ * (B_ / BM);   // 1024 CTAs -> 2 per SM
    expert_mlp_c64_kernel<<<grid, THREADS, SMEM_BYTES>>>(x, cond, b1, b2, out);
}